// round 4
// baseline (speedup 1.0000x reference)
#include <cuda_runtime.h>
#include <math.h>

#define BN   4
#define NG   16
#define NP   64
#define SZ   32
#define HH   640
#define WW   640
#define NPIX 1024
#define NBOX 80               // NG + NP
#define NPAIR 4096            // BN*NG*NP
#define C1V  6.5025f
#define C2V  58.5225f
#define THRESH 0.3f
#define PX   49               // x-padded pitch (8 left pad), odd -> conflict-free
#define PY   45               // y-padded pitch (5 top pad), odd -> conflict-free
#define GRID 592              // 148 SMs * 4 resident blocks (guaranteed by launch_bounds)
#define NBOXI (BN*NBOX*3)     // 960 crop items
#define PH1T  (NBOXI + 1)     // + validity item

// Normalized 11-tap Gaussian (sigma=1.5)
__constant__ float GK[11] = {
    0.00102838f, 0.00759870f, 0.03600077f, 0.10936100f, 0.21300570f,
    0.26601172f,
    0.21300570f, 0.10936100f, 0.03600077f, 0.00759870f, 0.00102838f
};

// Scratch (device globals; zero-initialized at module load)
__device__ __align__(128) float d_gcrop[BN*NG*3*NPIX];
__device__ __align__(128) float d_pcrop[BN*NP*3*NPIX];
__device__ __align__(128) float d_mug  [BN*NG*3*NPIX];
__device__ __align__(128) float d_sigg [BN*NG*3*NPIX];
__device__ __align__(128) float d_mup  [BN*NP*3*NPIX];
__device__ __align__(128) float d_sigp [BN*NP*3*NPIX];
__device__ int   d_valid_cnt;
__device__ int   d_valid_idx[NPAIR];
__device__ float d_v_ssim[NPAIR*3];
__device__ float d_v_l1  [NPAIR*3];
__device__ int          d_phase1;   // completed phase-1 items
__device__ unsigned int d_done;     // finalize ticket

// shared arena layout (float offsets)
//  phase1 crop : csh[0..1568) t1[1568..3008) t2[3008..4448) idx[4448..4640)
//  phase1 scan : sc = first 256 ints (only used by the block's LAST item)
//  phase2 pair : gsh[0..1568) psh[1568..3136) t1p[3136..4576) ws/wl[4576..4592)
//  finalize    : rs[0..256) rl[256..512)
#define SMEMF 4640

__global__ __launch_bounds__(256, 4)
void fused_kernel(const float* __restrict__ imgs,
                  const float* __restrict__ gt,
                  const float* __restrict__ pr,
                  float* __restrict__ out)
{
    __shared__ __align__(16) float S[SMEMF];
    __shared__ int s_last;
    const int tid = threadIdx.x;
    const int bid = blockIdx.x;

    float* csh = S;                 // [SZ*PX]
    float* t1  = S + 1568;          // [SZ*PY]
    float* t2  = S + 3008;          // [SZ*PY]
    int*   ix0s = (int*)(S + 4448);
    int*   ix1s = (int*)(S + 4480);
    int*   iy0s = (int*)(S + 4512);
    int*   iy1s = (int*)(S + 4544);
    float* fxs  = S + 4576;
    float* fys  = S + 4608;

    // ---- zero pads once for the crop phase (interiors overwritten per item)
    for (int p = tid; p < 4448; p += 256) S[p] = 0.f;
    __syncthreads();

    // ================= PHASE 1: crops + moments, then validity =============
    for (int it = bid; it < PH1T; it += GRID) {
        if (it == NBOXI) {
            // ---- validity + compaction (this is always a block's LAST item)
            int* sc = (int*)S;
            int flags = 0, cnt = 0;
            const int base = tid * 16;
            #pragma unroll
            for (int q = 0; q < 16; q++) {
                int pair = base + q;
                int b = pair >> 10, r = pair & 1023, i = r >> 6, j = r & 63;
                const float* gb = gt + (b*NG + i)*4;
                const float* pb = pr + (b*NP + j)*4;
                float gx = gb[0], gy = gb[1], gw = gb[2], gh = gb[3];
                float px = pb[0], py = pb[1], pw = pb[2], ph = pb[3];
                float tlx = fmaxf(gx - gw*0.5f, px - pw*0.5f);
                float tly = fmaxf(gy - gh*0.5f, py - ph*0.5f);
                float brx = fminf(gx + gw*0.5f, px + pw*0.5f);
                float bry = fminf(gy + gh*0.5f, py + ph*0.5f);
                float en = ((tlx < brx) && (tly < bry)) ? 1.f : 0.f;
                float ai = (brx - tlx) * (bry - tly) * en;
                float iou = ai / (gw*gh + pw*ph - ai + 1e-16f);
                bool valid = (iou > THRESH) && (pw > 2.f) && (ph > 2.f);
                if (valid) { flags |= (1 << q); cnt++; }
            }
            __syncthreads();          // arena reuse barrier
            sc[tid] = cnt;
            __syncthreads();
            for (int d = 1; d < 256; d <<= 1) {
                int v = sc[tid];
                if (tid >= d) v += sc[tid - d];
                __syncthreads();
                sc[tid] = v;
                __syncthreads();
            }
            int off = sc[tid] - cnt;
            #pragma unroll
            for (int q = 0; q < 16; q++)
                if (flags & (1 << q)) d_valid_idx[off++] = base + q;
            if (tid == 255) d_valid_cnt = sc[255];
            __threadfence();
            __syncthreads();
            if (tid == 0) atomicAdd(&d_phase1, 1);
            continue;
        }

        // ---- crop + moments for (b, box, channel)
        const int b   = it / (NBOX*3);
        const int rem = it % (NBOX*3);
        const int k   = rem / 3;
        const int c   = rem % 3;
        const bool isGT = (k < NG);
        const int  bi   = isGT ? (b*NG + k) : (b*NP + (k - NG));

        const float* box = isGT ? (gt + (b*NG + k)*4) : (pr + (b*NP + (k-NG))*4);
        float* crop_out  = (isGT ? d_gcrop : d_pcrop) + (size_t)bi*3*NPIX + c*NPIX;
        float* mu_out    = (isGT ? d_mug   : d_mup  ) + (size_t)bi*3*NPIX + c*NPIX;
        float* sig_out   = (isGT ? d_sigg  : d_sigp ) + (size_t)bi*3*NPIX + c*NPIX;

        if (tid < 64) {
            const float cx = box[0], cy = box[1], w = box[2], h = box[3];
            if (tid < 32) {
                float x0 = fminf(fmaxf(floorf(cx - w*0.5f), 0.f), (float)WW - 1.f);
                float x1 = fminf(fmaxf(floorf(cx + w*0.5f), 0.f), (float)WW);
                float wp = fmaxf(x1 - x0, 1.f);
                float dd = (float)tid + 0.5f;
                float sx = x0 + fminf(fmaxf(dd*wp/(float)SZ - 0.5f, 0.f), wp - 1.f);
                float fl = floorf(sx);
                fxs[tid]  = sx - fl;
                int i0    = (int)fl;
                ix0s[tid] = i0;
                ix1s[tid] = min(i0 + 1, (int)(x0 + wp - 1.f));
            } else {
                int t = tid - 32;
                float y0 = fminf(fmaxf(floorf(cy - h*0.5f), 0.f), (float)HH - 1.f);
                float y1 = fminf(fmaxf(floorf(cy + h*0.5f), 0.f), (float)HH);
                float hp = fmaxf(y1 - y0, 1.f);
                float dd = (float)t + 0.5f;
                float sy = y0 + fminf(fmaxf(dd*hp/(float)SZ - 0.5f, 0.f), hp - 1.f);
                float fl = floorf(sy);
                fys[t]  = sy - fl;
                int i0  = (int)fl;
                iy0s[t] = i0;
                iy1s[t] = min(i0 + 1, (int)(y0 + hp - 1.f));
            }
        }
        __syncthreads();

        // bilinear gather: thread -> (row = tid>>3, 4 px at xq = (tid&7)*4)
        {
            const int row = tid >> 3;
            const int xq  = (tid & 7) << 2;
            const float* ic = imgs + ((size_t)b*3 + c)*HH*WW;
            const int j0 = iy0s[row], j1 = iy1s[row];
            const float fy = fys[row];
            float4 vout;
            float* vp = (float*)&vout;
            #pragma unroll
            for (int q = 0; q < 4; q++) {
                int xx = xq + q;
                int i0 = ix0s[xx], i1 = ix1s[xx];
                float fx = fxs[xx];
                float v = ic[j0*WW + i0] * (1.f - fy) * (1.f - fx)
                        + ic[j0*WW + i1] * (1.f - fy) * fx
                        + ic[j1*WW + i0] * fy * (1.f - fx)
                        + ic[j1*WW + i1] * fy * fx;
                csh[row*PX + 8 + xx] = v;
                vp[q] = v;
            }
            *(float4*)(crop_out + row*SZ + xq) = vout;
        }
        __syncthreads();

        // horizontal conv: 4 outputs/thread from 14 shared loads
        {
            const int row = tid >> 3;
            const int xq  = (tid & 7) << 2;
            const float* base = csh + row*PX + xq + 3;
            float in[14], sq[14];
            #pragma unroll
            for (int k2 = 0; k2 < 14; k2++) { in[k2] = base[k2]; sq[k2] = in[k2]*in[k2]; }
            #pragma unroll
            for (int q = 0; q < 4; q++) {
                float a = 0.f, bb = 0.f;
                #pragma unroll
                for (int t = 0; t < 11; t++) {
                    a  = fmaf(GK[t], in[q+t], a);
                    bb = fmaf(GK[t], sq[q+t], bb);
                }
                t1[(xq+q)*PY + row + 5] = a;
                t2[(xq+q)*PY + row + 5] = bb;
            }
        }
        __syncthreads();

        // vertical conv: thread -> (col x = tid&31, 4 rows at yq=(tid>>5)*4)
        {
            const int x  = tid & 31;
            const int yq = (tid >> 5) << 2;
            const float* b1 = t1 + x*PY + yq;
            const float* b2 = t2 + x*PY + yq;
            float u1[14], u2[14];
            #pragma unroll
            for (int k2 = 0; k2 < 14; k2++) { u1[k2] = b1[k2]; u2[k2] = b2[k2]; }
            #pragma unroll
            for (int q = 0; q < 4; q++) {
                float a = 0.f, bb = 0.f;
                #pragma unroll
                for (int t = 0; t < 11; t++) {
                    a  = fmaf(GK[t], u1[q+t], a);
                    bb = fmaf(GK[t], u2[q+t], bb);
                }
                mu_out [(yq+q)*SZ + x] = a;
                sig_out[(yq+q)*SZ + x] = bb - a*a;
            }
        }
        __threadfence();
        __syncthreads();                 // also the arena-reuse barrier
        if (tid == 0) atomicAdd(&d_phase1, 1);
    }

    // ================= PHASE 2: pairs (after spin) ==========================
    float* gsh = S;                 // [SZ*PX]
    float* psh = S + 1568;          // [SZ*PX]
    float* t1p = S + 3136;          // [SZ*PY]
    float* ws  = S + 4576;          // [8]
    float* wl  = S + 4584;          // [8]

    __syncthreads();
    for (int p = tid; p < 4576; p += 256) S[p] = 0.f;   // re-zero pair arena pads
    if (tid == 0) {
        while (atomicAdd(&d_phase1, 0) < PH1T) __nanosleep(64);
        __threadfence();
    }
    __syncthreads();

    const int nitems = d_valid_cnt * 3;

    for (int itp = bid; itp < nitems; itp += GRID) {
        const int v = itp / 3;
        const int c = itp - v*3;
        const int pair = d_valid_idx[v];
        const int b = pair >> 10, r = pair & 1023, i = r >> 6, j = r & 63;

        const float* gbase = d_gcrop + ((size_t)(b*NG + i)*3 + c)*NPIX;
        const float* pbase = d_pcrop + ((size_t)(b*NP + j)*3 + c)*NPIX;
        const float* mug   = d_mug   + ((size_t)(b*NG + i)*3 + c)*NPIX;
        const float* sigg  = d_sigg  + ((size_t)(b*NG + i)*3 + c)*NPIX;
        const float* mup   = d_mup   + ((size_t)(b*NP + j)*3 + c)*NPIX;
        const float* sigp  = d_sigp  + ((size_t)(b*NP + j)*3 + c)*NPIX;

        {
            const int row = tid >> 3;
            const int xq  = (tid & 7) << 2;
            float4 g4 = *(const float4*)(gbase + row*SZ + xq);
            float4 p4 = *(const float4*)(pbase + row*SZ + xq);
            float* gp = (float*)&g4;
            float* pp = (float*)&p4;
            #pragma unroll
            for (int q = 0; q < 4; q++) {
                gsh[row*PX + 8 + xq + q] = gp[q];
                psh[row*PX + 8 + xq + q] = pp[q];
            }
        }
        __syncthreads();

        {
            const int row = tid >> 3;
            const int xq  = (tid & 7) << 2;
            const float* gb2 = gsh + row*PX + xq + 3;
            const float* pb2 = psh + row*PX + xq + 3;
            float in[14];
            #pragma unroll
            for (int k2 = 0; k2 < 14; k2++) in[k2] = gb2[k2] * pb2[k2];
            #pragma unroll
            for (int q = 0; q < 4; q++) {
                float a = 0.f;
                #pragma unroll
                for (int t = 0; t < 11; t++) a = fmaf(GK[t], in[q+t], a);
                t1p[(xq+q)*PY + row + 5] = a;
            }
        }
        __syncthreads();

        float acc_ssim = 0.f, acc_l1 = 0.f;
        {
            const int x  = tid & 31;
            const int yq = (tid >> 5) << 2;
            const float* b1 = t1p + x*PY + yq;
            float u[14];
            #pragma unroll
            for (int k2 = 0; k2 < 14; k2++) u[k2] = b1[k2];
            #pragma unroll
            for (int q = 0; q < 4; q++) {
                float egp = 0.f;
                #pragma unroll
                for (int t = 0; t < 11; t++) egp = fmaf(GK[t], u[q+t], egp);
                const int p = (yq+q)*SZ + x;
                float mg  = mug [p];
                float mp_ = mup [p];
                float sg  = sigg[p];
                float sp  = sigp[p];
                float sgp = egp - mg*mp_;
                float num = (2.f*mg*mp_ + C1V) * (2.f*sgp + C2V);
                float den = (mg*mg + mp_*mp_ + C1V) * (sg + sp + C2V);
                acc_ssim += num / den;
                float gv = gsh[(yq+q)*PX + 8 + x];
                float pv = psh[(yq+q)*PX + 8 + x];
                acc_l1  += fabsf(gv - pv) * (1.0f/255.0f);
            }
        }

        #pragma unroll
        for (int o = 16; o > 0; o >>= 1) {
            acc_ssim += __shfl_down_sync(0xffffffffu, acc_ssim, o);
            acc_l1   += __shfl_down_sync(0xffffffffu, acc_l1,   o);
        }
        if ((tid & 31) == 0) { ws[tid >> 5] = acc_ssim; wl[tid >> 5] = acc_l1; }
        __syncthreads();
        if (tid == 0) {
            float s = 0.f, l = 0.f;
            #pragma unroll
            for (int w = 0; w < 8; w++) { s += ws[w]; l += wl[w]; }
            d_v_ssim[itp] = s;
            d_v_l1  [itp] = l;
        }
        __syncthreads();
    }

    // ================= PHASE 3: fused finalize (last block) =================
    if (tid == 0) {
        __threadfence();
        unsigned int t = atomicAdd(&d_done, 1u);
        s_last = (t == GRID - 1u) ? 1 : 0;
    }
    __syncthreads();
    if (!s_last) return;
    __threadfence();

    float* rs = S;
    float* rl = S + 256;
    float cs = 0.f, cl = 0.f;
    for (int p = tid; p < nitems; p += 256) { cs += d_v_ssim[p]; cl += d_v_l1[p]; }
    rs[tid] = cs; rl[tid] = cl;
    __syncthreads();
    #pragma unroll
    for (int s = 128; s > 0; s >>= 1) {
        if (tid < s) { rs[tid] += rs[tid+s]; rl[tid] += rl[tid+s]; }
        __syncthreads();
    }
    if (tid == 0) {
        float cnt   = (float)d_valid_cnt;
        float denom = fmaxf(cnt, 1.f) * 3.0f * (float)NPIX;
        float loss  = rl[0] / denom + 1.f - rs[0] / denom;
        out[0] = (cnt > 0.f) ? loss : 0.f;
        // reset counters for the next graph replay
        d_phase1 = 0;
        d_done   = 0u;
    }
}

extern "C" void kernel_launch(void* const* d_in, const int* in_sizes, int n_in,
                              void* d_out, int out_size)
{
    const float* imgs = (const float*)d_in[0];   // (4,3,640,640)
    const float* gt   = (const float*)d_in[1];   // (4,16,4)
    const float* pr   = (const float*)d_in[2];   // (4,64,4)
    float* out = (float*)d_out;

    fused_kernel<<<GRID, 256>>>(imgs, gt, pr, out);
}

// round 5
// speedup vs baseline: 1.1277x; 1.1277x over previous
#include <cuda_runtime.h>
#include <math.h>

#define BN   4
#define NG   16
#define NP   64
#define SZ   32
#define HH   640
#define WW   640
#define NPIX 1024
#define NBOX 80               // NG + NP
#define NPAIR 4096            // BN*NG*NP
#define C1V  6.5025f
#define C2V  58.5225f
#define THRESH 0.3f
#define PX   49               // x-padded pitch (8 left pad), odd -> conflict-free
#define PY   45               // y-padded pitch (5 top pad), odd -> conflict-free
#define GRID 592              // 148 SMs * 4 resident blocks (launch_bounds guarantees co-residency)
#define CROPB (GRID-1)        // 591 crop-worker blocks
#define NBOXI (BN*NBOX*3)     // 960 crop items

// Normalized 11-tap Gaussian (sigma=1.5)
__constant__ float GK[11] = {
    0.00102838f, 0.00759870f, 0.03600077f, 0.10936100f, 0.21300570f,
    0.26601172f,
    0.21300570f, 0.10936100f, 0.03600077f, 0.00759870f, 0.00102838f
};

// Scratch (device globals; zero-initialized at module load; reset each run)
__device__ __align__(128) float d_gcrop[BN*NG*3*NPIX];
__device__ __align__(128) float d_pcrop[BN*NP*3*NPIX];
__device__ __align__(128) float d_mug  [BN*NG*3*NPIX];
__device__ __align__(128) float d_sigg [BN*NG*3*NPIX];
__device__ __align__(128) float d_mup  [BN*NP*3*NPIX];
__device__ __align__(128) float d_sigp [BN*NP*3*NPIX];
__device__ int   d_valid_cnt;
__device__ int   d_valid_idx[NPAIR];
__device__ float d_v_ssim[NPAIR*3];
__device__ float d_v_l1  [NPAIR*3];
__device__ int   d_ready[NBOXI];    // per crop-item done flags
__device__ int   d_valid_ready;
__device__ unsigned int d_done;     // finalize ticket

#define SMEMF 4640

__device__ __forceinline__ void spin_flag(const int* f) {
    while (*(volatile const int*)f == 0) __nanosleep(32);
}

__global__ __launch_bounds__(256, 4)
void fused_kernel(const float* __restrict__ imgs,
                  const float* __restrict__ gt,
                  const float* __restrict__ pr,
                  float* __restrict__ out)
{
    __shared__ __align__(16) float S[SMEMF];
    __shared__ int s_last;
    const int tid = threadIdx.x;
    const int bid = blockIdx.x;

    float* csh = S;                 // [SZ*PX]  crop tile / pair product tile
    float* t1  = S + 1568;          // [SZ*PY]
    float* t2  = S + 3008;          // [SZ*PY]  (phase-1 only)
    int*   ix0s = (int*)(S + 4448);
    int*   ix1s = (int*)(S + 4480);
    int*   iy0s = (int*)(S + 4512);
    int*   iy1s = (int*)(S + 4544);
    float* fxs  = S + 4576;
    float* fys  = S + 4608;
    float* ws   = S + 4448;         // [8] (phase-2 reuse of idx area)
    float* wl   = S + 4456;         // [8]

    // zero arena once (pads stay zero; interiors overwritten per item)
    for (int p = tid; p < 4448; p += 256) S[p] = 0.f;
    __syncthreads();

    // ================= PHASE 1 =============================================
    if (bid == 0) {
        // ---- validity + compaction (runs immediately)
        int* sc = (int*)S;           // safe: block 0 does no crop items
        int flags = 0, cnt = 0;
        const int base = tid * 16;
        #pragma unroll
        for (int q = 0; q < 16; q++) {
            int pair = base + q;
            int b = pair >> 10, r = pair & 1023, i = r >> 6, j = r & 63;
            const float* gb = gt + (b*NG + i)*4;
            const float* pb = pr + (b*NP + j)*4;
            float gx = gb[0], gy = gb[1], gw = gb[2], gh = gb[3];
            float px = pb[0], py = pb[1], pw = pb[2], ph = pb[3];
            float tlx = fmaxf(gx - gw*0.5f, px - pw*0.5f);
            float tly = fmaxf(gy - gh*0.5f, py - ph*0.5f);
            float brx = fminf(gx + gw*0.5f, px + pw*0.5f);
            float bry = fminf(gy + gh*0.5f, py + ph*0.5f);
            float en = ((tlx < brx) && (tly < bry)) ? 1.f : 0.f;
            float ai = (brx - tlx) * (bry - tly) * en;
            float iou = ai / (gw*gh + pw*ph - ai + 1e-16f);
            bool valid = (iou > THRESH) && (pw > 2.f) && (ph > 2.f);
            if (valid) { flags |= (1 << q); cnt++; }
        }
        __syncthreads();
        sc[tid] = cnt;
        __syncthreads();
        for (int d = 1; d < 256; d <<= 1) {
            int v = sc[tid];
            if (tid >= d) v += sc[tid - d];
            __syncthreads();
            sc[tid] = v;
            __syncthreads();
        }
        int off = sc[tid] - cnt;
        #pragma unroll
        for (int q = 0; q < 16; q++)
            if (flags & (1 << q)) d_valid_idx[off++] = base + q;
        if (tid == 255) d_valid_cnt = sc[255];
        __threadfence();
        __syncthreads();
        if (tid == 0) { d_valid_ready = 1; }
        // re-zero the scan area (it overlapped csh pads used in phase 2)
        __syncthreads();
        for (int p = tid; p < 256; p += 256) S[p] = 0.f;
        __syncthreads();
    } else {
        for (int it = bid - 1; it < NBOXI; it += CROPB) {
            const int b   = it / (NBOX*3);
            const int rem = it % (NBOX*3);
            const int k   = rem / 3;
            const int c   = rem % 3;
            const bool isGT = (k < NG);
            const int  bi   = isGT ? (b*NG + k) : (b*NP + (k - NG));

            const float* box = isGT ? (gt + (b*NG + k)*4) : (pr + (b*NP + (k-NG))*4);
            float* crop_out  = (isGT ? d_gcrop : d_pcrop) + (size_t)bi*3*NPIX + c*NPIX;
            float* mu_out    = (isGT ? d_mug   : d_mup  ) + (size_t)bi*3*NPIX + c*NPIX;
            float* sig_out   = (isGT ? d_sigg  : d_sigp ) + (size_t)bi*3*NPIX + c*NPIX;

            if (tid < 64) {
                const float cx = box[0], cy = box[1], w = box[2], h = box[3];
                if (tid < 32) {
                    float x0 = fminf(fmaxf(floorf(cx - w*0.5f), 0.f), (float)WW - 1.f);
                    float x1 = fminf(fmaxf(floorf(cx + w*0.5f), 0.f), (float)WW);
                    float wp = fmaxf(x1 - x0, 1.f);
                    float dd = (float)tid + 0.5f;
                    float sx = x0 + fminf(fmaxf(dd*wp/(float)SZ - 0.5f, 0.f), wp - 1.f);
                    float fl = floorf(sx);
                    fxs[tid]  = sx - fl;
                    int i0    = (int)fl;
                    ix0s[tid] = i0;
                    ix1s[tid] = min(i0 + 1, (int)(x0 + wp - 1.f));
                } else {
                    int t = tid - 32;
                    float y0 = fminf(fmaxf(floorf(cy - h*0.5f), 0.f), (float)HH - 1.f);
                    float y1 = fminf(fmaxf(floorf(cy + h*0.5f), 0.f), (float)HH);
                    float hp = fmaxf(y1 - y0, 1.f);
                    float dd = (float)t + 0.5f;
                    float sy = y0 + fminf(fmaxf(dd*hp/(float)SZ - 0.5f, 0.f), hp - 1.f);
                    float fl = floorf(sy);
                    fys[t]  = sy - fl;
                    int i0  = (int)fl;
                    iy0s[t] = i0;
                    iy1s[t] = min(i0 + 1, (int)(y0 + hp - 1.f));
                }
            }
            __syncthreads();

            {   // bilinear gather
                const int row = tid >> 3;
                const int xq  = (tid & 7) << 2;
                const float* ic = imgs + ((size_t)b*3 + c)*HH*WW;
                const int j0 = iy0s[row], j1 = iy1s[row];
                const float fy = fys[row];
                float4 vout;
                float* vp = (float*)&vout;
                #pragma unroll
                for (int q = 0; q < 4; q++) {
                    int xx = xq + q;
                    int i0 = ix0s[xx], i1 = ix1s[xx];
                    float fx = fxs[xx];
                    float v = ic[j0*WW + i0] * (1.f - fy) * (1.f - fx)
                            + ic[j0*WW + i1] * (1.f - fy) * fx
                            + ic[j1*WW + i0] * fy * (1.f - fx)
                            + ic[j1*WW + i1] * fy * fx;
                    csh[row*PX + 8 + xx] = v;
                    vp[q] = v;
                }
                *(float4*)(crop_out + row*SZ + xq) = vout;
            }
            __syncthreads();

            {   // horizontal conv of x and x^2
                const int row = tid >> 3;
                const int xq  = (tid & 7) << 2;
                const float* base = csh + row*PX + xq + 3;
                float in[14], sq[14];
                #pragma unroll
                for (int k2 = 0; k2 < 14; k2++) { in[k2] = base[k2]; sq[k2] = in[k2]*in[k2]; }
                #pragma unroll
                for (int q = 0; q < 4; q++) {
                    float a = 0.f, bb = 0.f;
                    #pragma unroll
                    for (int t = 0; t < 11; t++) {
                        a  = fmaf(GK[t], in[q+t], a);
                        bb = fmaf(GK[t], sq[q+t], bb);
                    }
                    t1[(xq+q)*PY + row + 5] = a;
                    t2[(xq+q)*PY + row + 5] = bb;
                }
            }
            __syncthreads();

            {   // vertical conv -> mu, sigma
                const int x  = tid & 31;
                const int yq = (tid >> 5) << 2;
                const float* b1 = t1 + x*PY + yq;
                const float* b2 = t2 + x*PY + yq;
                float u1[14], u2[14];
                #pragma unroll
                for (int k2 = 0; k2 < 14; k2++) { u1[k2] = b1[k2]; u2[k2] = b2[k2]; }
                #pragma unroll
                for (int q = 0; q < 4; q++) {
                    float a = 0.f, bb = 0.f;
                    #pragma unroll
                    for (int t = 0; t < 11; t++) {
                        a  = fmaf(GK[t], u1[q+t], a);
                        bb = fmaf(GK[t], u2[q+t], bb);
                    }
                    mu_out [(yq+q)*SZ + x] = a;
                    sig_out[(yq+q)*SZ + x] = bb - a*a;
                }
            }
            __threadfence();
            __syncthreads();
            if (tid == 0) d_ready[it] = 1;
            __syncthreads();   // flag store done before smem reuse next iter
        }
    }

    // ================= PHASE 2: pairs, gated by per-item flags ==============
    if (tid == 0) { spin_flag(&d_valid_ready); __threadfence(); }
    __syncthreads();
    const int nitems = d_valid_cnt * 3;

    for (int itp = bid; itp < nitems; itp += GRID) {
        const int v = itp / 3;
        const int c = itp - v*3;
        const int pair = d_valid_idx[v];
        const int b = pair >> 10, r = pair & 1023, i = r >> 6, j = r & 63;

        // wait for the two crop items this pair needs
        if (tid == 0) {
            spin_flag(&d_ready[b*(NBOX*3) + i*3 + c]);
            spin_flag(&d_ready[b*(NBOX*3) + (NG + j)*3 + c]);
            __threadfence();
        }
        __syncthreads();

        const float* gbase = d_gcrop + ((size_t)(b*NG + i)*3 + c)*NPIX;
        const float* pbase = d_pcrop + ((size_t)(b*NP + j)*3 + c)*NPIX;
        const float* mug   = d_mug   + ((size_t)(b*NG + i)*3 + c)*NPIX;
        const float* sigg  = d_sigg  + ((size_t)(b*NG + i)*3 + c)*NPIX;
        const float* mup   = d_mup   + ((size_t)(b*NP + j)*3 + c)*NPIX;
        const float* sigp  = d_sigp  + ((size_t)(b*NP + j)*3 + c)*NPIX;

        float acc_ssim = 0.f, acc_l1 = 0.f;

        {   // load g,p; product -> smem; L1 in registers
            const int row = tid >> 3;
            const int xq  = (tid & 7) << 2;
            float4 g4 = *(const float4*)(gbase + row*SZ + xq);
            float4 p4 = *(const float4*)(pbase + row*SZ + xq);
            const float* gp = (const float*)&g4;
            const float* pp = (const float*)&p4;
            #pragma unroll
            for (int q = 0; q < 4; q++) {
                csh[row*PX + 8 + xq + q] = gp[q] * pp[q];
                acc_l1 += fabsf(gp[q] - pp[q]) * (1.0f/255.0f);
            }
        }
        __syncthreads();

        {   // horizontal conv of product
            const int row = tid >> 3;
            const int xq  = (tid & 7) << 2;
            const float* base = csh + row*PX + xq + 3;
            float in[14];
            #pragma unroll
            for (int k2 = 0; k2 < 14; k2++) in[k2] = base[k2];
            #pragma unroll
            for (int q = 0; q < 4; q++) {
                float a = 0.f;
                #pragma unroll
                for (int t = 0; t < 11; t++) a = fmaf(GK[t], in[q+t], a);
                t1[(xq+q)*PY + row + 5] = a;
            }
        }
        __syncthreads();

        {   // vertical conv + SSIM
            const int x  = tid & 31;
            const int yq = (tid >> 5) << 2;
            const float* b1 = t1 + x*PY + yq;
            float u[14];
            #pragma unroll
            for (int k2 = 0; k2 < 14; k2++) u[k2] = b1[k2];
            #pragma unroll
            for (int q = 0; q < 4; q++) {
                float egp = 0.f;
                #pragma unroll
                for (int t = 0; t < 11; t++) egp = fmaf(GK[t], u[q+t], egp);
                const int p = (yq+q)*SZ + x;
                float mg  = mug [p];
                float mp_ = mup [p];
                float sg  = sigg[p];
                float sp  = sigp[p];
                float sgp = egp - mg*mp_;
                float num = (2.f*mg*mp_ + C1V) * (2.f*sgp + C2V);
                float den = (mg*mg + mp_*mp_ + C1V) * (sg + sp + C2V);
                acc_ssim += num / den;
            }
        }

        #pragma unroll
        for (int o = 16; o > 0; o >>= 1) {
            acc_ssim += __shfl_down_sync(0xffffffffu, acc_ssim, o);
            acc_l1   += __shfl_down_sync(0xffffffffu, acc_l1,   o);
        }
        if ((tid & 31) == 0) { ws[tid >> 5] = acc_ssim; wl[tid >> 5] = acc_l1; }
        __syncthreads();
        if (tid == 0) {
            float s = 0.f, l = 0.f;
            #pragma unroll
            for (int w = 0; w < 8; w++) { s += ws[w]; l += wl[w]; }
            d_v_ssim[itp] = s;
            d_v_l1  [itp] = l;
        }
        __syncthreads();
    }

    // ================= PHASE 3: fused finalize (last block) =================
    if (tid == 0) {
        __threadfence();
        unsigned int t = atomicAdd(&d_done, 1u);
        s_last = (t == GRID - 1u) ? 1 : 0;
    }
    __syncthreads();
    if (!s_last) return;
    __threadfence();

    float* rs = S;
    float* rl = S + 256;
    float cs = 0.f, cl = 0.f;
    for (int p = tid; p < nitems; p += 256) { cs += d_v_ssim[p]; cl += d_v_l1[p]; }
    rs[tid] = cs; rl[tid] = cl;
    __syncthreads();
    #pragma unroll
    for (int s = 128; s > 0; s >>= 1) {
        if (tid < s) { rs[tid] += rs[tid+s]; rl[tid] += rl[tid+s]; }
        __syncthreads();
    }
    // reset flags for next graph replay
    for (int p = tid; p < NBOXI; p += 256) d_ready[p] = 0;
    if (tid == 0) {
        float cnt   = (float)d_valid_cnt;
        float denom = fmaxf(cnt, 1.f) * 3.0f * (float)NPIX;
        float loss  = rl[0] / denom + 1.f - rs[0] / denom;
        out[0] = (cnt > 0.f) ? loss : 0.f;
        d_valid_ready = 0;
        d_done        = 0u;
    }
}

extern "C" void kernel_launch(void* const* d_in, const int* in_sizes, int n_in,
                              void* d_out, int out_size)
{
    const float* imgs = (const float*)d_in[0];   // (4,3,640,640)
    const float* gt   = (const float*)d_in[1];   // (4,16,4)
    const float* pr   = (const float*)d_in[2];   // (4,64,4)
    float* out = (float*)d_out;

    fused_kernel<<<GRID, 256>>>(imgs, gt, pr, out);
}